// round 1
// baseline (speedup 1.0000x reference)
#include <cuda_runtime.h>

#define Bn 128
#define Tn 256
#define Cn 384
#define Hn 64
#define Mtot (Bn*Tn)   // 32768 rows

// scratch for q,k,v projections (device globals: no allocation allowed)
__device__ float g_q[Mtot*Hn];
__device__ float g_k[Mtot*Hn];
__device__ float g_v[Mtot*Hn];

// ---------------------------------------------------------------------------
// QKV projection: out = x @ W, x:[32768,384], W:[384,64]
// grid (256, 1, 3)  blockIdx.z selects q/k/v.  256 threads.
// Block tile 128x64, K-tile 32. Thread tile 8x4.
// ---------------------------------------------------------------------------
__global__ __launch_bounds__(256) void qkv_proj(
    const float* __restrict__ x,
    const float* __restrict__ Wq,
    const float* __restrict__ Wk,
    const float* __restrict__ Wv)
{
    __shared__ float Xs[32][132];   // [k][m], padded (132 -> 4-way STS conflict max, LDS clean)
    __shared__ float Ws[32][64];    // [k][n]

    const float* W;
    float* outp;
    if (blockIdx.z == 0)      { W = Wq; outp = g_q; }
    else if (blockIdx.z == 1) { W = Wk; outp = g_k; }
    else                      { W = Wv; outp = g_v; }

    const int tid = threadIdx.x;
    const int m0  = blockIdx.x * 128;
    const int tm  = tid >> 4;        // 0..15
    const int tn  = tid & 15;        // 0..15

    float acc[8][4];
    #pragma unroll
    for (int u = 0; u < 8; u++)
        #pragma unroll
        for (int v = 0; v < 4; v++) acc[u][v] = 0.f;

    for (int kb = 0; kb < Cn; kb += 32) {
        // load X tile 128x32, transposed into Xs[k][m]
        #pragma unroll
        for (int i = 0; i < 4; i++) {
            int idx = tid + i * 256;          // 0..1023 float4s
            int row = idx >> 3;               // 0..127
            int cg  = idx & 7;                // 0..7
            float4 xv = *(const float4*)(x + (size_t)(m0 + row) * Cn + kb + cg * 4);
            Xs[cg*4+0][row] = xv.x;
            Xs[cg*4+1][row] = xv.y;
            Xs[cg*4+2][row] = xv.z;
            Xs[cg*4+3][row] = xv.w;
        }
        // load W tile 32x64
        #pragma unroll
        for (int i = 0; i < 2; i++) {
            int idx = tid + i * 256;          // 0..511 float4s
            int row = idx >> 4;               // 0..31
            int cg  = idx & 15;               // 0..15
            *(float4*)&Ws[row][cg*4] = *(const float4*)(W + (size_t)(kb + row) * Hn + cg * 4);
        }
        __syncthreads();

        #pragma unroll
        for (int kk = 0; kk < 32; kk++) {
            float4 a0 = *(const float4*)&Xs[kk][tm*8];
            float4 a1 = *(const float4*)&Xs[kk][tm*8 + 4];
            float4 bv = *(const float4*)&Ws[kk][tn*4];
            float a[8] = {a0.x,a0.y,a0.z,a0.w,a1.x,a1.y,a1.z,a1.w};
            float bb[4] = {bv.x,bv.y,bv.z,bv.w};
            #pragma unroll
            for (int u = 0; u < 8; u++)
                #pragma unroll
                for (int v = 0; v < 4; v++)
                    acc[u][v] += a[u] * bb[v];
        }
        __syncthreads();
    }

    #pragma unroll
    for (int u = 0; u < 8; u++) {
        float4 o = make_float4(acc[u][0], acc[u][1], acc[u][2], acc[u][3]);
        *(float4*)(outp + (size_t)(m0 + tm*8 + u) * Hn + tn * 4) = o;
    }
}

// ---------------------------------------------------------------------------
// Fused causal attention.
// NOTE (faithful to reference): wei[t,s] = k[t] . q[s]  (K = rows, Q = cols),
// scale = 1/sqrt(384), causal tril on (t,s), softmax over s, out = wei @ v.
//
// grid (4, 128): blockIdx.x = 64-row t-tile (qt), blockIdx.y = batch.
// 256 threads, 16x16 thread grid, 4x4 register tiles for both GEMMs.
// Full score row kept in smem (T=256) -> plain softmax (no online rescale).
// Smem tiles XOR-swizzled (group g at row i stored at g ^ (i&15)).
// ---------------------------------------------------------------------------
#define SW(i,g) ((g) ^ ((i) & 15))

__global__ __launch_bounds__(256) void attn_kernel(float* __restrict__ out)
{
    extern __shared__ float sm[];
    float* Rt = sm;              // k-rows tile  [64][64] swizzled
    float* Ct = sm + 4096;       // q-rows tile  [64][64] swizzled
    float* Vs = sm + 8192;       // v tile       [64][64] swizzled
    float* S  = sm + 12288;      // scores       [64][260]
    float* rs = S + 64 * 260;    // [64] reciprocal row sums

    const int tid = threadIdx.x;
    const int qt  = blockIdx.x;        // t-tile 0..3
    const int b   = blockIdx.y;
    const int rowbase = b * Tn + qt * 64;
    const float scale = rsqrtf((float)Cn);

    const int ty = tid >> 4, tx = tid & 15;
    const int i0 = ty * 4,   j0 = tx * 4;

    // load R tile (k rows), swizzled
    #pragma unroll
    for (int i = 0; i < 4; i++) {
        int idx = tid + i * 256;          // 0..1023
        int r = idx >> 4, g = idx & 15;
        float4 v = *(const float4*)(g_k + (size_t)(rowbase + r) * Hn + g * 4);
        *(float4*)&Rt[r * 64 + 4 * SW(r, g)] = v;
    }

    // ---- score tiles: S[t][s] for s-tiles st = 0..qt ----
    for (int st = 0; st <= qt; st++) {
        #pragma unroll
        for (int i = 0; i < 4; i++) {
            int idx = tid + i * 256;
            int r = idx >> 4, g = idx & 15;
            float4 v = *(const float4*)(g_q + (size_t)(b * Tn + st * 64 + r) * Hn + g * 4);
            *(float4*)&Ct[r * 64 + 4 * SW(r, g)] = v;
        }
        __syncthreads();

        float acc[4][4];
        #pragma unroll
        for (int u = 0; u < 4; u++)
            #pragma unroll
            for (int v = 0; v < 4; v++) acc[u][v] = 0.f;

        #pragma unroll
        for (int d4 = 0; d4 < 16; d4++) {
            float4 rv[4], cv[4];
            #pragma unroll
            for (int u = 0; u < 4; u++)
                rv[u] = *(const float4*)&Rt[(i0 + u) * 64 + 4 * SW(i0 + u, d4)];
            #pragma unroll
            for (int v = 0; v < 4; v++)
                cv[v] = *(const float4*)&Ct[(j0 + v) * 64 + 4 * SW(j0 + v, d4)];
            #pragma unroll
            for (int u = 0; u < 4; u++)
                #pragma unroll
                for (int v = 0; v < 4; v++)
                    acc[u][v] += rv[u].x * cv[v].x + rv[u].y * cv[v].y
                               + rv[u].z * cv[v].z + rv[u].w * cv[v].w;
        }

        #pragma unroll
        for (int u = 0; u < 4; u++) {
            int ig = qt * 64 + i0 + u;
            #pragma unroll
            for (int v = 0; v < 4; v++) {
                int jg = st * 64 + j0 + v;
                float val = (jg <= ig) ? acc[u][v] * scale : -1e30f;
                S[(i0 + u) * 260 + jg] = val;
            }
        }
        __syncthreads();
    }

    // ---- softmax over valid columns [0, (qt+1)*64) ----
    {
        const int warp = tid >> 5, lane = tid & 31;
        const int Ltot = (qt + 1) * 64;
        for (int rr = 0; rr < 8; rr++) {
            int r = warp * 8 + rr;
            float* Srow = S + r * 260;
            float m = -1e30f;
            for (int c = lane; c < Ltot; c += 32) m = fmaxf(m, Srow[c]);
            #pragma unroll
            for (int o = 16; o > 0; o >>= 1) m = fmaxf(m, __shfl_xor_sync(0xffffffffu, m, o));
            float ssum = 0.f;
            for (int c = lane; c < Ltot; c += 32) {
                float e = __expf(Srow[c] - m);
                Srow[c] = e;
                ssum += e;
            }
            #pragma unroll
            for (int o = 16; o > 0; o >>= 1) ssum += __shfl_xor_sync(0xffffffffu, ssum, o);
            if (lane == 0) rs[r] = 1.f / ssum;
        }
    }
    __syncthreads();

    // ---- O = P @ V ----
    float oacc[4][4];
    #pragma unroll
    for (int u = 0; u < 4; u++)
        #pragma unroll
        for (int v = 0; v < 4; v++) oacc[u][v] = 0.f;

    for (int st = 0; st <= qt; st++) {
        #pragma unroll
        for (int i = 0; i < 4; i++) {
            int idx = tid + i * 256;
            int r = idx >> 4, g = idx & 15;
            float4 v = *(const float4*)(g_v + (size_t)(b * Tn + st * 64 + r) * Hn + g * 4);
            *(float4*)&Vs[r * 64 + 4 * SW(r, g)] = v;
        }
        __syncthreads();

        #pragma unroll 8
        for (int s = 0; s < 64; s++) {
            float4 vv = *(const float4*)&Vs[s * 64 + 4 * SW(s, tx)];
            float p0 = S[(i0 + 0) * 260 + st * 64 + s];
            float p1 = S[(i0 + 1) * 260 + st * 64 + s];
            float p2 = S[(i0 + 2) * 260 + st * 64 + s];
            float p3 = S[(i0 + 3) * 260 + st * 64 + s];
            oacc[0][0] += p0 * vv.x; oacc[0][1] += p0 * vv.y; oacc[0][2] += p0 * vv.z; oacc[0][3] += p0 * vv.w;
            oacc[1][0] += p1 * vv.x; oacc[1][1] += p1 * vv.y; oacc[1][2] += p1 * vv.z; oacc[1][3] += p1 * vv.w;
            oacc[2][0] += p2 * vv.x; oacc[2][1] += p2 * vv.y; oacc[2][2] += p2 * vv.z; oacc[2][3] += p2 * vv.w;
            oacc[3][0] += p3 * vv.x; oacc[3][1] += p3 * vv.y; oacc[3][2] += p3 * vv.z; oacc[3][3] += p3 * vv.w;
        }
        __syncthreads();
    }

    #pragma unroll
    for (int u = 0; u < 4; u++) {
        float inv = rs[i0 + u];
        float4 o = make_float4(oacc[u][0] * inv, oacc[u][1] * inv,
                               oacc[u][2] * inv, oacc[u][3] * inv);
        *(float4*)(out + (size_t)(rowbase + i0 + u) * Hn + tx * 4) = o;
    }
}

// ---------------------------------------------------------------------------
extern "C" void kernel_launch(void* const* d_in, const int* in_sizes, int n_in,
                              void* d_out, int out_size)
{
    const float* x  = (const float*)d_in[0];
    const float* Wq = (const float*)d_in[1];
    const float* Wk = (const float*)d_in[2];
    const float* Wv = (const float*)d_in[3];
    float* out = (float*)d_out;

    const int attn_smem = (4096 * 3 + 64 * 260 + 64) * (int)sizeof(float); // 115968 B
    // attribute set is idempotent; first (non-captured) correctness call makes it stick
    cudaFuncSetAttribute(attn_kernel, cudaFuncAttributeMaxDynamicSharedMemorySize, attn_smem);

    qkv_proj<<<dim3(Mtot / 128, 1, 3), 256>>>(x, Wq, Wk, Wv);
    attn_kernel<<<dim3(4, Bn), 256, attn_smem>>>(out);
}

// round 2
// speedup vs baseline: 1.0775x; 1.0775x over previous
#include <cuda_runtime.h>

#define Bn 128
#define Tn 256
#define Cn 384
#define Hn 64
#define Mtot (Bn*Tn)   // 32768 rows

typedef unsigned long long u64;

__device__ __forceinline__ u64 pack2(float a, float b) {
    u64 r; asm("mov.b64 %0,{%1,%2};" : "=l"(r) : "f"(a), "f"(b)); return r;
}
__device__ __forceinline__ void unpack2(u64 v, float& a, float& b) {
    asm("mov.b64 {%0,%1},%2;" : "=f"(a), "=f"(b) : "l"(v));
}
__device__ __forceinline__ u64 fma2(u64 a, u64 b, u64 c) {
    u64 d; asm("fma.rn.f32x2 %0,%1,%2,%3;" : "=l"(d) : "l"(a), "l"(b), "l"(c)); return d;
}
__device__ __forceinline__ u64 mul2(u64 a, u64 b) {
    u64 d; asm("mul.rn.f32x2 %0,%1,%2;" : "=l"(d) : "l"(a), "l"(b)); return d;
}

// scratch for q,k,v projections (device globals: no allocation allowed)
__device__ float g_q[Mtot*Hn];
__device__ float g_k[Mtot*Hn];
__device__ float g_v[Mtot*Hn];

// ---------------------------------------------------------------------------
// QKV projection: out = x @ W, x:[32768,384], W:[384,64]
// grid (256, 1, 3). 256 threads. Block tile 128x64, K-tile 32, thread 8x4.
// f32x2: accumulators paired over M (pairs packed in Xs[k][m] layout),
// B broadcast-packed. 16 FFMA2 + 8 MOV per k-step vs 32 FFMA before.
// ---------------------------------------------------------------------------
__global__ __launch_bounds__(256) void qkv_proj(
    const float* __restrict__ x,
    const float* __restrict__ Wq,
    const float* __restrict__ Wk,
    const float* __restrict__ Wv)
{
    __shared__ float Xs[32][132];   // [k][m]
    __shared__ float Ws[32][64];    // [k][n]

    const float* W;
    float* outp;
    if (blockIdx.z == 0)      { W = Wq; outp = g_q; }
    else if (blockIdx.z == 1) { W = Wk; outp = g_k; }
    else                      { W = Wv; outp = g_v; }

    const int tid = threadIdx.x;
    const int m0  = blockIdx.x * 128;
    const int tm  = tid >> 4;        // 0..15
    const int tn  = tid & 15;        // 0..15

    // acc2[u][v]: rows (tm*8+2u, tm*8+2u+1), col tn*4+v, packed f32x2
    u64 acc2[4][4];
    #pragma unroll
    for (int u = 0; u < 4; u++)
        #pragma unroll
        for (int v = 0; v < 4; v++) acc2[u][v] = 0ull;

    for (int kb = 0; kb < Cn; kb += 32) {
        // load X tile 128x32, transposed into Xs[k][m]
        #pragma unroll
        for (int i = 0; i < 4; i++) {
            int idx = tid + i * 256;
            int row = idx >> 3;               // 0..127
            int cg  = idx & 7;                // 0..7
            float4 xv = *(const float4*)(x + (size_t)(m0 + row) * Cn + kb + cg * 4);
            Xs[cg*4+0][row] = xv.x;
            Xs[cg*4+1][row] = xv.y;
            Xs[cg*4+2][row] = xv.z;
            Xs[cg*4+3][row] = xv.w;
        }
        // load W tile 32x64
        #pragma unroll
        for (int i = 0; i < 2; i++) {
            int idx = tid + i * 256;
            int row = idx >> 4;               // 0..31
            int cg  = idx & 15;               // 0..15
            *(float4*)&Ws[row][cg*4] = *(const float4*)(W + (size_t)(kb + row) * Hn + cg * 4);
        }
        __syncthreads();

        #pragma unroll
        for (int kk = 0; kk < 32; kk++) {
            ulonglong2 a01 = *(const ulonglong2*)&Xs[kk][tm*8];      // {m0,m1},{m2,m3}
            ulonglong2 a23 = *(const ulonglong2*)&Xs[kk][tm*8 + 4];  // {m4,m5},{m6,m7}
            float4 bv = *(const float4*)&Ws[kk][tn*4];
            u64 b2[4];
            b2[0] = pack2(bv.x, bv.x);
            b2[1] = pack2(bv.y, bv.y);
            b2[2] = pack2(bv.z, bv.z);
            b2[3] = pack2(bv.w, bv.w);
            #pragma unroll
            for (int v = 0; v < 4; v++) {
                acc2[0][v] = fma2(a01.x, b2[v], acc2[0][v]);
                acc2[1][v] = fma2(a01.y, b2[v], acc2[1][v]);
                acc2[2][v] = fma2(a23.x, b2[v], acc2[2][v]);
                acc2[3][v] = fma2(a23.y, b2[v], acc2[3][v]);
            }
        }
        __syncthreads();
    }

    #pragma unroll
    for (int u = 0; u < 4; u++) {
        float lo[4], hi[4];
        #pragma unroll
        for (int v = 0; v < 4; v++) unpack2(acc2[u][v], lo[v], hi[v]);
        int r = m0 + tm*8 + 2*u;
        *(float4*)(outp + (size_t)r       * Hn + tn * 4) = make_float4(lo[0], lo[1], lo[2], lo[3]);
        *(float4*)(outp + (size_t)(r + 1) * Hn + tn * 4) = make_float4(hi[0], hi[1], hi[2], hi[3]);
    }
}

// ---------------------------------------------------------------------------
// Fused causal attention, flash-style online softmax (no full score buffer).
// Faithful to reference: wei[t,s] = k[t].q[s], scale 1/sqrt(384),
// causal tril over (t,s), softmax over s, out = wei @ v.
//
// grid (4, 128): t-tile (heavy tiles first), batch. 256 threads, 16x16 grid,
// 4x4 thread tiles. smem = Rt + CQ(=P, reused) + Vs = exactly 48KB -> with
// <=128 regs (launch_bounds 256,2) we get 2 CTAs/SM (16 warps).
// Score GEMM: f32x2 paired over the d-reduction (no packing movs).
// PV GEMM:    f32x2 paired over h, P broadcast-packed.
// ---------------------------------------------------------------------------
#define SW(i,g) ((g) ^ ((i) & 15))

__global__ __launch_bounds__(256, 2) void attn_kernel(float* __restrict__ out)
{
    __shared__ float Rt[64 * 64];   // k rows tile, swizzled
    __shared__ float CQ[64 * 64];   // q tile during scores; reused as P tile
    __shared__ float Vs[64 * 64];   // v tile, swizzled

    const int tid = threadIdx.x;
    const int qt  = 3 - blockIdx.x;        // heavy tiles first
    const int b   = blockIdx.y;
    const int rowbase = b * Tn + qt * 64;
    const float scale = 0.051031036307982884f;  // 384^-0.5

    const int ty = tid >> 4, tx = tid & 15;
    const int i0 = ty * 4,   j0 = tx * 4;

    // load R tile (k rows), swizzled
    #pragma unroll
    for (int i = 0; i < 4; i++) {
        int idx = tid + i * 256;
        int r = idx >> 4, g = idx & 15;
        float4 v = *(const float4*)(g_k + (size_t)(rowbase + r) * Hn + g * 4);
        *(float4*)&Rt[r * 64 + 4 * SW(r, g)] = v;
    }

    float mrow[4], lrow[4];
    u64 acc_o[4][2];
    #pragma unroll
    for (int u = 0; u < 4; u++) {
        mrow[u] = -1e30f; lrow[u] = 0.f;
        acc_o[u][0] = 0ull; acc_o[u][1] = 0ull;
    }

    for (int st = 0; st <= qt; st++) {
        // load q tile and v tile for this s-block
        #pragma unroll
        for (int i = 0; i < 4; i++) {
            int idx = tid + i * 256;
            int r = idx >> 4, g = idx & 15;
            float4 vq = *(const float4*)(g_q + (size_t)(b * Tn + st * 64 + r) * Hn + g * 4);
            *(float4*)&CQ[r * 64 + 4 * SW(r, g)] = vq;
            float4 vv = *(const float4*)(g_v + (size_t)(b * Tn + st * 64 + r) * Hn + g * 4);
            *(float4*)&Vs[r * 64 + 4 * SW(r, g)] = vv;
        }
        __syncthreads();

        // ---- scores: S = Rt . CQ^T (reduction over d, f32x2-paired) ----
        u64 s2[4][4];
        #pragma unroll
        for (int u = 0; u < 4; u++)
            #pragma unroll
            for (int v = 0; v < 4; v++) s2[u][v] = 0ull;

        #pragma unroll
        for (int d4 = 0; d4 < 16; d4++) {
            ulonglong2 rv[4], cv[4];
            #pragma unroll
            for (int u = 0; u < 4; u++)
                rv[u] = *(const ulonglong2*)&Rt[(i0 + u) * 64 + 4 * SW(i0 + u, d4)];
            #pragma unroll
            for (int v = 0; v < 4; v++)
                cv[v] = *(const ulonglong2*)&CQ[(j0 + v) * 64 + 4 * SW(j0 + v, d4)];
            #pragma unroll
            for (int u = 0; u < 4; u++)
                #pragma unroll
                for (int v = 0; v < 4; v++) {
                    s2[u][v] = fma2(rv[u].x, cv[v].x, s2[u][v]);
                    s2[u][v] = fma2(rv[u].y, cv[v].y, s2[u][v]);
                }
        }

        float sc[4][4];
        #pragma unroll
        for (int u = 0; u < 4; u++)
            #pragma unroll
            for (int v = 0; v < 4; v++) {
                float lo, hi; unpack2(s2[u][v], lo, hi);
                sc[u][v] = (lo + hi) * scale;
            }

        if (st == qt) {  // causal mask within diagonal tile: keep j<=i
            #pragma unroll
            for (int u = 0; u < 4; u++)
                #pragma unroll
                for (int v = 0; v < 4; v++)
                    if (j0 + v > i0 + u) sc[u][v] = -1e30f;
        }

        __syncthreads();   // everyone done reading CQ before P overwrites it

        // ---- online softmax update (row stats shared across the 16 tx lanes) ----
        #pragma unroll
        for (int u = 0; u < 4; u++) {
            float tmax = fmaxf(fmaxf(sc[u][0], sc[u][1]), fmaxf(sc[u][2], sc[u][3]));
            #pragma unroll
            for (int o = 1; o < 16; o <<= 1)
                tmax = fmaxf(tmax, __shfl_xor_sync(0xffffffffu, tmax, o));
            float mnew = fmaxf(mrow[u], tmax);
            float f = __expf(mrow[u] - mnew);
            mrow[u] = mnew;
            lrow[u] *= f;
            u64 f2 = pack2(f, f);
            acc_o[u][0] = mul2(acc_o[u][0], f2);
            acc_o[u][1] = mul2(acc_o[u][1], f2);
            float psum = 0.f;
            #pragma unroll
            for (int v = 0; v < 4; v++) {
                float p = __expf(sc[u][v] - mnew);
                sc[u][v] = p;
                psum += p;
            }
            #pragma unroll
            for (int o = 1; o < 16; o <<= 1)
                psum += __shfl_xor_sync(0xffffffffu, psum, o);
            lrow[u] += psum;
            // write P row chunk (swizzled float4, same pattern as tile loads)
            *(float4*)&CQ[(i0 + u) * 64 + 4 * SW(i0 + u, tx)] =
                make_float4(sc[u][0], sc[u][1], sc[u][2], sc[u][3]);
        }
        __syncthreads();   // P visible

        // ---- O += P @ V (f32x2 paired over h) ----
        #pragma unroll 2
        for (int sg = 0; sg < 16; sg++) {
            int pofs[4];
            #pragma unroll
            for (int u = 0; u < 4; u++)
                pofs[u] = (i0 + u) * 64 + 4 * SW(i0 + u, sg);
            #pragma unroll
            for (int c = 0; c < 4; c++) {
                int s = sg * 4 + c;
                ulonglong2 vv = *(const ulonglong2*)&Vs[s * 64 + 4 * SW(s, tx)];
                #pragma unroll
                for (int u = 0; u < 4; u++) {
                    float p = CQ[pofs[u] + c];
                    u64 p2 = pack2(p, p);
                    acc_o[u][0] = fma2(p2, vv.x, acc_o[u][0]);
                    acc_o[u][1] = fma2(p2, vv.y, acc_o[u][1]);
                }
            }
        }
        __syncthreads();   // done with CQ(P)/Vs before next tile's loads
    }

    #pragma unroll
    for (int u = 0; u < 4; u++) {
        float inv = 1.f / lrow[u];
        float o0, o1, o2, o3;
        unpack2(acc_o[u][0], o0, o1);
        unpack2(acc_o[u][1], o2, o3);
        *(float4*)(out + (size_t)(rowbase + i0 + u) * Hn + tx * 4) =
            make_float4(o0 * inv, o1 * inv, o2 * inv, o3 * inv);
    }
}

// ---------------------------------------------------------------------------
extern "C" void kernel_launch(void* const* d_in, const int* in_sizes, int n_in,
                              void* d_out, int out_size)
{
    const float* x  = (const float*)d_in[0];
    const float* Wq = (const float*)d_in[1];
    const float* Wk = (const float*)d_in[2];
    const float* Wv = (const float*)d_in[3];
    float* out = (float*)d_out;

    qkv_proj<<<dim3(Mtot / 128, 1, 3), 256>>>(x, Wq, Wk, Wv);
    attn_kernel<<<dim3(4, Bn), 256>>>(out);
}

// round 3
// speedup vs baseline: 1.1371x; 1.0553x over previous
#include <cuda_runtime.h>

#define Bn 128
#define Tn 256
#define Cn 384
#define Hn 64
#define Mtot (Bn*Tn)   // 32768 rows

typedef unsigned int u32;
typedef unsigned long long u64;

__device__ __forceinline__ u64 pack2(float a, float b) {
    u64 r; asm("mov.b64 %0,{%1,%2};" : "=l"(r) : "f"(a), "f"(b)); return r;
}
__device__ __forceinline__ void unpack2(u64 v, float& a, float& b) {
    asm("mov.b64 {%0,%1},%2;" : "=f"(a), "=f"(b) : "l"(v));
}
__device__ __forceinline__ u64 fma2(u64 a, u64 b, u64 c) {
    u64 d; asm("fma.rn.f32x2 %0,%1,%2,%3;" : "=l"(d) : "l"(a), "l"(b), "l"(c)); return d;
}
__device__ __forceinline__ u64 mul2(u64 a, u64 b) {
    u64 d; asm("mul.rn.f32x2 %0,%1,%2;" : "=l"(d) : "l"(a), "l"(b)); return d;
}

// tf32 helpers
__device__ __forceinline__ u32 cvt_tf32(float f) {
    u32 u; asm("cvt.rna.tf32.f32 %0, %1;" : "=r"(u) : "f"(f)); return u;
}
__device__ __forceinline__ void mma8(float* d, const u32* a, const u32* b) {
    asm volatile(
        "mma.sync.aligned.m16n8k8.row.col.f32.tf32.tf32.f32 "
        "{%0,%1,%2,%3},{%4,%5,%6,%7},{%8,%9},{%0,%1,%2,%3};"
        : "+f"(d[0]), "+f"(d[1]), "+f"(d[2]), "+f"(d[3])
        : "r"(a[0]), "r"(a[1]), "r"(a[2]), "r"(a[3]), "r"(b[0]), "r"(b[1]));
}

// scratch for q,k,v projections (device globals: no allocation allowed)
__device__ float g_q[Mtot*Hn];
__device__ float g_k[Mtot*Hn];
__device__ float g_v[Mtot*Hn];

// ---------------------------------------------------------------------------
// QKV projection on tensor cores: out = x @ W, x:[32768,384], W:[384,64]
// 3xTF32 (hi/lo split) for ~fp32 accuracy.
// grid (256,1,3), 256 threads = 8 warps in 4(M)x2(N). Block tile 128x64.
// Warp tile 32x32 = 2 m-tiles(16) x 4 n-tiles(8), K-step 8, K-tile 32.
// Smem pads chosen so all fragment LDS are bank-conflict-free:
//   Xs[128][36]: banks (4*g + t) unique; Ws[32][72]: banks (8*t + g) unique.
// ---------------------------------------------------------------------------
__global__ __launch_bounds__(256) void qkv_mma(
    const float* __restrict__ x,
    const float* __restrict__ Wq,
    const float* __restrict__ Wk,
    const float* __restrict__ Wv)
{
    __shared__ float Xs[128][36];
    __shared__ float Ws[32][72];

    const float* W;
    float* outp;
    if (blockIdx.z == 0)      { W = Wq; outp = g_q; }
    else if (blockIdx.z == 1) { W = Wk; outp = g_k; }
    else                      { W = Wv; outp = g_v; }

    const int tid    = threadIdx.x;
    const int lane   = tid & 31;
    const int wid    = tid >> 5;
    const int warp_m = wid >> 1;        // 0..3
    const int warp_n = wid & 1;         // 0..1
    const int g4     = lane >> 2;       // 0..7
    const int t4     = lane & 3;        // 0..3
    const int m0     = blockIdx.x * 128;

    float acc[2][4][4];
    #pragma unroll
    for (int mt = 0; mt < 2; mt++)
        #pragma unroll
        for (int nt = 0; nt < 4; nt++)
            #pragma unroll
            for (int i = 0; i < 4; i++) acc[mt][nt][i] = 0.f;

    for (int kb = 0; kb < Cn; kb += 32) {
        // stage X tile 128x32
        #pragma unroll
        for (int i = 0; i < 4; i++) {
            int idx = tid + i * 256;
            int row = idx >> 3, cg = idx & 7;
            *(float4*)&Xs[row][cg*4] =
                *(const float4*)(x + (size_t)(m0 + row) * Cn + kb + cg * 4);
        }
        // stage W tile 32x64
        #pragma unroll
        for (int i = 0; i < 2; i++) {
            int idx = tid + i * 256;
            int row = idx >> 4, cg = idx & 15;
            *(float4*)&Ws[row][cg*4] =
                *(const float4*)(W + (size_t)(kb + row) * Hn + cg * 4);
        }
        __syncthreads();

        #pragma unroll
        for (int ks = 0; ks < 4; ks++) {
            const int k0 = ks * 8 + t4;

            u32 ahi[2][4], alo[2][4];
            #pragma unroll
            for (int mt = 0; mt < 2; mt++) {
                int r = warp_m * 32 + mt * 16 + g4;
                float v0 = Xs[r][k0];
                float v1 = Xs[r + 8][k0];
                float v2 = Xs[r][k0 + 4];
                float v3 = Xs[r + 8][k0 + 4];
                ahi[mt][0] = cvt_tf32(v0); alo[mt][0] = cvt_tf32(v0 - __uint_as_float(ahi[mt][0]));
                ahi[mt][1] = cvt_tf32(v1); alo[mt][1] = cvt_tf32(v1 - __uint_as_float(ahi[mt][1]));
                ahi[mt][2] = cvt_tf32(v2); alo[mt][2] = cvt_tf32(v2 - __uint_as_float(ahi[mt][2]));
                ahi[mt][3] = cvt_tf32(v3); alo[mt][3] = cvt_tf32(v3 - __uint_as_float(ahi[mt][3]));
            }

            u32 bhi[4][2], blo[4][2];
            #pragma unroll
            for (int nt = 0; nt < 4; nt++) {
                int col = warp_n * 32 + nt * 8 + g4;
                float w0 = Ws[ks * 8 + t4][col];
                float w1 = Ws[ks * 8 + t4 + 4][col];
                bhi[nt][0] = cvt_tf32(w0); blo[nt][0] = cvt_tf32(w0 - __uint_as_float(bhi[nt][0]));
                bhi[nt][1] = cvt_tf32(w1); blo[nt][1] = cvt_tf32(w1 - __uint_as_float(bhi[nt][1]));
            }

            #pragma unroll
            for (int mt = 0; mt < 2; mt++)
                #pragma unroll
                for (int nt = 0; nt < 4; nt++) {
                    mma8(acc[mt][nt], alo[mt], bhi[nt]);   // lo*hi
                    mma8(acc[mt][nt], ahi[mt], blo[nt]);   // hi*lo
                    mma8(acc[mt][nt], ahi[mt], bhi[nt]);   // hi*hi
                }
        }
        __syncthreads();
    }

    // epilogue: c0,c1 -> (row, col..col+1), c2,c3 -> (row+8, ...)
    #pragma unroll
    for (int mt = 0; mt < 2; mt++) {
        int row = m0 + warp_m * 32 + mt * 16 + g4;
        #pragma unroll
        for (int nt = 0; nt < 4; nt++) {
            int col = warp_n * 32 + nt * 8 + t4 * 2;
            *(float2*)(outp + (size_t)row       * Hn + col) = make_float2(acc[mt][nt][0], acc[mt][nt][1]);
            *(float2*)(outp + (size_t)(row + 8) * Hn + col) = make_float2(acc[mt][nt][2], acc[mt][nt][3]);
        }
    }
}

// ---------------------------------------------------------------------------
// Fused causal attention (unchanged from round 2: passing, 92us).
// ---------------------------------------------------------------------------
#define SW(i,g) ((g) ^ ((i) & 15))

__global__ __launch_bounds__(256, 2) void attn_kernel(float* __restrict__ out)
{
    __shared__ float Rt[64 * 64];
    __shared__ float CQ[64 * 64];
    __shared__ float Vs[64 * 64];

    const int tid = threadIdx.x;
    const int qt  = 3 - blockIdx.x;
    const int b   = blockIdx.y;
    const int rowbase = b * Tn + qt * 64;
    const float scale = 0.051031036307982884f;  // 384^-0.5

    const int ty = tid >> 4, tx = tid & 15;
    const int i0 = ty * 4,   j0 = tx * 4;

    #pragma unroll
    for (int i = 0; i < 4; i++) {
        int idx = tid + i * 256;
        int r = idx >> 4, g = idx & 15;
        float4 v = *(const float4*)(g_k + (size_t)(rowbase + r) * Hn + g * 4);
        *(float4*)&Rt[r * 64 + 4 * SW(r, g)] = v;
    }

    float mrow[4], lrow[4];
    u64 acc_o[4][2];
    #pragma unroll
    for (int u = 0; u < 4; u++) {
        mrow[u] = -1e30f; lrow[u] = 0.f;
        acc_o[u][0] = 0ull; acc_o[u][1] = 0ull;
    }

    for (int st = 0; st <= qt; st++) {
        #pragma unroll
        for (int i = 0; i < 4; i++) {
            int idx = tid + i * 256;
            int r = idx >> 4, g = idx & 15;
            float4 vq = *(const float4*)(g_q + (size_t)(b * Tn + st * 64 + r) * Hn + g * 4);
            *(float4*)&CQ[r * 64 + 4 * SW(r, g)] = vq;
            float4 vv = *(const float4*)(g_v + (size_t)(b * Tn + st * 64 + r) * Hn + g * 4);
            *(float4*)&Vs[r * 64 + 4 * SW(r, g)] = vv;
        }
        __syncthreads();

        u64 s2[4][4];
        #pragma unroll
        for (int u = 0; u < 4; u++)
            #pragma unroll
            for (int v = 0; v < 4; v++) s2[u][v] = 0ull;

        #pragma unroll
        for (int d4 = 0; d4 < 16; d4++) {
            ulonglong2 rv[4], cv[4];
            #pragma unroll
            for (int u = 0; u < 4; u++)
                rv[u] = *(const ulonglong2*)&Rt[(i0 + u) * 64 + 4 * SW(i0 + u, d4)];
            #pragma unroll
            for (int v = 0; v < 4; v++)
                cv[v] = *(const ulonglong2*)&CQ[(j0 + v) * 64 + 4 * SW(j0 + v, d4)];
            #pragma unroll
            for (int u = 0; u < 4; u++)
                #pragma unroll
                for (int v = 0; v < 4; v++) {
                    s2[u][v] = fma2(rv[u].x, cv[v].x, s2[u][v]);
                    s2[u][v] = fma2(rv[u].y, cv[v].y, s2[u][v]);
                }
        }

        float sc[4][4];
        #pragma unroll
        for (int u = 0; u < 4; u++)
            #pragma unroll
            for (int v = 0; v < 4; v++) {
                float lo, hi; unpack2(s2[u][v], lo, hi);
                sc[u][v] = (lo + hi) * scale;
            }

        if (st == qt) {
            #pragma unroll
            for (int u = 0; u < 4; u++)
                #pragma unroll
                for (int v = 0; v < 4; v++)
                    if (j0 + v > i0 + u) sc[u][v] = -1e30f;
        }

        __syncthreads();

        #pragma unroll
        for (int u = 0; u < 4; u++) {
            float tmax = fmaxf(fmaxf(sc[u][0], sc[u][1]), fmaxf(sc[u][2], sc[u][3]));
            #pragma unroll
            for (int o = 1; o < 16; o <<= 1)
                tmax = fmaxf(tmax, __shfl_xor_sync(0xffffffffu, tmax, o));
            float mnew = fmaxf(mrow[u], tmax);
            float f = __expf(mrow[u] - mnew);
            mrow[u] = mnew;
            lrow[u] *= f;
            u64 f2 = pack2(f, f);
            acc_o[u][0] = mul2(acc_o[u][0], f2);
            acc_o[u][1] = mul2(acc_o[u][1], f2);
            float psum = 0.f;
            #pragma unroll
            for (int v = 0; v < 4; v++) {
                float p = __expf(sc[u][v] - mnew);
                sc[u][v] = p;
                psum += p;
            }
            #pragma unroll
            for (int o = 1; o < 16; o <<= 1)
                psum += __shfl_xor_sync(0xffffffffu, psum, o);
            lrow[u] += psum;
            *(float4*)&CQ[(i0 + u) * 64 + 4 * SW(i0 + u, tx)] =
                make_float4(sc[u][0], sc[u][1], sc[u][2], sc[u][3]);
        }
        __syncthreads();

        #pragma unroll 2
        for (int sg = 0; sg < 16; sg++) {
            int pofs[4];
            #pragma unroll
            for (int u = 0; u < 4; u++)
                pofs[u] = (i0 + u) * 64 + 4 * SW(i0 + u, sg);
            #pragma unroll
            for (int c = 0; c < 4; c++) {
                int s = sg * 4 + c;
                ulonglong2 vv = *(const ulonglong2*)&Vs[s * 64 + 4 * SW(s, tx)];
                #pragma unroll
                for (int u = 0; u < 4; u++) {
                    float p = CQ[pofs[u] + c];
                    u64 p2 = pack2(p, p);
                    acc_o[u][0] = fma2(p2, vv.x, acc_o[u][0]);
                    acc_o[u][1] = fma2(p2, vv.y, acc_o[u][1]);
                }
            }
        }
        __syncthreads();
    }

    #pragma unroll
    for (int u = 0; u < 4; u++) {
        float inv = 1.f / lrow[u];
        float o0, o1, o2, o3;
        unpack2(acc_o[u][0], o0, o1);
        unpack2(acc_o[u][1], o2, o3);
        *(float4*)(out + (size_t)(rowbase + i0 + u) * Hn + tx * 4) =
            make_float4(o0 * inv, o1 * inv, o2 * inv, o3 * inv);
    }
}

// ---------------------------------------------------------------------------
extern "C" void kernel_launch(void* const* d_in, const int* in_sizes, int n_in,
                              void* d_out, int out_size)
{
    const float* x  = (const float*)d_in[0];
    const float* Wq = (const float*)d_in[1];
    const float* Wk = (const float*)d_in[2];
    const float* Wv = (const float*)d_in[3];
    float* out = (float*)d_out;

    qkv_mma<<<dim3(Mtot / 128, 1, 3), 256>>>(x, Wq, Wk, Wv);
    attn_kernel<<<dim3(4, Bn), 256>>>(out);
}

// round 4
// speedup vs baseline: 2.7392x; 2.4090x over previous
#include <cuda_runtime.h>

#define Bn 128
#define Tn 256
#define Cn 384
#define Hn 64
#define Mtot (Bn*Tn)   // 32768 rows

typedef unsigned int u32;
typedef unsigned short u16;

// scratch for q,k,v projections (device globals: no allocation allowed)
__device__ float g_q[Mtot*Hn];
__device__ float g_k[Mtot*Hn];
__device__ float g_v[Mtot*Hn];

// ---------------------------------------------------------------------------
// helpers
// ---------------------------------------------------------------------------
__device__ __forceinline__ u32 sptr(const void* p) {
    return (u32)__cvta_generic_to_shared(p);
}
__device__ __forceinline__ void ldm4(u32& r0, u32& r1, u32& r2, u32& r3, u32 a) {
    asm volatile("ldmatrix.sync.aligned.m8n8.x4.shared.b16 {%0,%1,%2,%3},[%4];"
                 : "=r"(r0), "=r"(r1), "=r"(r2), "=r"(r3) : "r"(a));
}
__device__ __forceinline__ void ldm4t(u32& r0, u32& r1, u32& r2, u32& r3, u32 a) {
    asm volatile("ldmatrix.sync.aligned.m8n8.x4.trans.shared.b16 {%0,%1,%2,%3},[%4];"
                 : "=r"(r0), "=r"(r1), "=r"(r2), "=r"(r3) : "r"(a));
}
__device__ __forceinline__ void mma_bf16(float* c, const u32* a, const u32* b) {
    asm volatile(
        "mma.sync.aligned.m16n8k16.row.col.f32.bf16.bf16.f32 "
        "{%0,%1,%2,%3},{%4,%5,%6,%7},{%8,%9},{%0,%1,%2,%3};"
        : "+f"(c[0]), "+f"(c[1]), "+f"(c[2]), "+f"(c[3])
        : "r"(a[0]), "r"(a[1]), "r"(a[2]), "r"(a[3]), "r"(b[0]), "r"(b[1]));
}
// bf16 hi = truncation of fp32 (exact residual); lo = rn-bf16 of residual.
__device__ __forceinline__ u32 pack_hi(float a, float b) {
    return (__float_as_uint(a) >> 16) | (__float_as_uint(b) & 0xFFFF0000u);
}
__device__ __forceinline__ u32 pack_lo(float a, float b) {
    float ra = a - __uint_as_float(__float_as_uint(a) & 0xFFFF0000u);
    float rb = b - __uint_as_float(__float_as_uint(b) & 0xFFFF0000u);
    u32 r;  // first PTX source -> upper half
    asm("cvt.rn.bf16x2.f32 %0,%1,%2;" : "=r"(r) : "f"(rb), "f"(ra));
    return r;
}
__device__ __forceinline__ float ex2(float x) {
    float y; asm("ex2.approx.ftz.f32 %0,%1;" : "=f"(y) : "f"(x)); return y;
}

// ---------------------------------------------------------------------------
// QKV projection, bf16x3 on tensor cores. out = x @ W.
// grid (3, 256): z fastest so the 3 blocks sharing an X tile are wave-adjacent
// (X tile L2-hot on 2nd/3rd read). 256 threads = 8 warps, 4(M)x2(N),
// warp tile 32x32, block tile 128x64, K-tile 32 (2 k16 steps).
// smem strides: X 40 (80B=5x16B), W 72 (144B=9x16B) -> ldmatrix conflict-free.
// ---------------------------------------------------------------------------
__global__ __launch_bounds__(256, 2) void qkv_bf16(
    const float* __restrict__ x,
    const float* __restrict__ Wq,
    const float* __restrict__ Wk,
    const float* __restrict__ Wv)
{
    __shared__ __align__(16) u16 Xhi[128 * 40], Xlo[128 * 40];
    __shared__ __align__(16) u16 Whi[32 * 72],  Wlo[32 * 72];

    const int z = blockIdx.x;
    const float* W;
    float* outp;
    if (z == 0)      { W = Wq; outp = g_q; }
    else if (z == 1) { W = Wk; outp = g_k; }
    else             { W = Wv; outp = g_v; }

    const int tid    = threadIdx.x;
    const int lane   = tid & 31;
    const int wid    = tid >> 5;
    const int warp_m = wid >> 1;        // 0..3
    const int warp_n = wid & 1;         // 0..1
    const int g4     = lane >> 2;
    const int t4     = lane & 3;
    const int m0     = blockIdx.y * 128;

    // ldmatrix lane address components
    const int r8  = lane & 7;
    const int sel = lane >> 3;
    const int a_row = (sel & 1) * 8 + r8;     // A: row offset
    const int a_kof = (sel >> 1) * 8;         // A: k offset
    const int b_krow = (sel & 1) * 8 + r8;    // B(trans): k-row offset
    const int b_nof  = (sel >> 1) * 8;        // B(trans): n offset

    const u32 XhiS = sptr(Xhi), XloS = sptr(Xlo);
    const u32 WhiS = sptr(Whi), WloS = sptr(Wlo);

    float acc[2][4][4];
    #pragma unroll
    for (int mt = 0; mt < 2; mt++)
        #pragma unroll
        for (int nt = 0; nt < 4; nt++)
            #pragma unroll
            for (int e = 0; e < 4; e++) acc[mt][nt][e] = 0.f;

    for (int kb = 0; kb < Cn; kb += 32) {
        // stage X tile 128x32 -> bf16 hi/lo
        #pragma unroll
        for (int i = 0; i < 4; i++) {
            int idx = tid + i * 256;
            int row = idx >> 3, cg = idx & 7;
            float4 v = *(const float4*)(x + (size_t)(m0 + row) * Cn + kb + cg * 4);
            u32* H = (u32*)&Xhi[row * 40 + cg * 4];
            u32* L = (u32*)&Xlo[row * 40 + cg * 4];
            H[0] = pack_hi(v.x, v.y); H[1] = pack_hi(v.z, v.w);
            L[0] = pack_lo(v.x, v.y); L[1] = pack_lo(v.z, v.w);
        }
        // stage W tile 32x64
        #pragma unroll
        for (int i = 0; i < 2; i++) {
            int idx = tid + i * 256;
            int row = idx >> 4, cg = idx & 15;
            float4 v = *(const float4*)(W + (size_t)(kb + row) * Hn + cg * 4);
            u32* H = (u32*)&Whi[row * 72 + cg * 4];
            u32* L = (u32*)&Wlo[row * 72 + cg * 4];
            H[0] = pack_hi(v.x, v.y); H[1] = pack_hi(v.z, v.w);
            L[0] = pack_lo(v.x, v.y); L[1] = pack_lo(v.z, v.w);
        }
        __syncthreads();

        #pragma unroll
        for (int ks = 0; ks < 2; ks++) {
            const int k0 = ks * 16;
            u32 ah[2][4], al[2][4];
            #pragma unroll
            for (int mt = 0; mt < 2; mt++) {
                u32 off = 2u * ((warp_m * 32 + mt * 16 + a_row) * 40 + k0 + a_kof);
                ldm4(ah[mt][0], ah[mt][1], ah[mt][2], ah[mt][3], XhiS + off);
                ldm4(al[mt][0], al[mt][1], al[mt][2], al[mt][3], XloS + off);
            }
            u32 bh[2][4], bl[2][4];
            #pragma unroll
            for (int h = 0; h < 2; h++) {
                u32 off = 2u * ((k0 + b_krow) * 72 + warp_n * 32 + h * 16 + b_nof);
                ldm4t(bh[h][0], bh[h][1], bh[h][2], bh[h][3], WhiS + off);
                ldm4t(bl[h][0], bl[h][1], bl[h][2], bl[h][3], WloS + off);
            }
            #pragma unroll
            for (int mt = 0; mt < 2; mt++)
                #pragma unroll
                for (int h = 0; h < 2; h++)
                    #pragma unroll
                    for (int j = 0; j < 2; j++) {
                        float* c = acc[mt][h * 2 + j];
                        mma_bf16(c, ah[mt], &bh[h][2 * j]);
                        mma_bf16(c, ah[mt], &bl[h][2 * j]);
                        mma_bf16(c, al[mt], &bh[h][2 * j]);
                    }
        }
        __syncthreads();
    }

    #pragma unroll
    for (int mt = 0; mt < 2; mt++) {
        int row = m0 + warp_m * 32 + mt * 16 + g4;
        #pragma unroll
        for (int nt = 0; nt < 4; nt++) {
            int col = warp_n * 32 + nt * 8 + 2 * t4;
            *(float2*)(outp + (size_t)row       * Hn + col) = make_float2(acc[mt][nt][0], acc[mt][nt][1]);
            *(float2*)(outp + (size_t)(row + 8) * Hn + col) = make_float2(acc[mt][nt][2], acc[mt][nt][3]);
        }
    }
}

// ---------------------------------------------------------------------------
// Fused causal attention, flash-style online softmax on bf16x3 mma fragments.
// Faithful: wei[t,s] = k[t].q[s], scale 384^-0.5, tril, softmax over s, @ v.
// grid (4,128): qt = 3-bx heavy-first; 8 warps 4(M-rows-of-t)x2(N).
// S warp tile 16x32; O warp tile 16x32. Q smem buffer reused for P (bf16 hi/lo).
// smem stride 72 u16 (144B = 9x16B) -> conflict-free ldmatrix.
// ---------------------------------------------------------------------------
#define ATTN_SMEM (6*9216 + 3*64*4 + 128*4)

__global__ __launch_bounds__(256, 2) void attn_bf16(float* __restrict__ out)
{
    extern __shared__ __align__(16) char sm[];
    u16* Khi  = (u16*)sm;
    u16* Klo  = (u16*)(sm + 9216);
    u16* QPhi = (u16*)(sm + 2 * 9216);
    u16* QPlo = (u16*)(sm + 3 * 9216);
    u16* Vhi  = (u16*)(sm + 4 * 9216);
    u16* Vlo  = (u16*)(sm + 5 * 9216);
    float* m_s = (float*)(sm + 6 * 9216);
    float* l_s = m_s + 64;
    float* f_s = m_s + 128;
    float* pm  = m_s + 192;   // [2][64]

    const int tid  = threadIdx.x;
    const int lane = tid & 31;
    const int wid  = tid >> 5;
    const int warp_m = wid >> 1;
    const int warp_n = wid & 1;
    const int g4 = lane >> 2;
    const int t4 = lane & 3;
    const int r8  = lane & 7;
    const int sel = lane >> 3;
    const int a_row = (sel & 1) * 8 + r8;
    const int a_kof = (sel >> 1) * 8;
    const int bt_krow = (sel & 1) * 8 + r8;   // trans-B (V)
    const int bt_nof  = (sel >> 1) * 8;
    const int bn_row = (sel >> 1) * 8 + r8;   // non-trans-B (Q)
    const int bn_kof = (sel & 1) * 8;

    const int qt = 3 - blockIdx.x;
    const int b  = blockIdx.y;
    const int rowg0 = b * Tn + qt * 64;
    // scale * log2(e): softmax computed base-2
    const float SCL = 0.051031036307982884f * 1.4426950408889634f;

    const u32 KhiS = sptr(Khi), KloS = sptr(Klo);
    const u32 QPhiS = sptr(QPhi), QPloS = sptr(QPlo);
    const u32 VhiS = sptr(Vhi), VloS = sptr(Vlo);

    if (tid < 64) { m_s[tid] = -1e30f; l_s[tid] = 0.f; }
    // stage K tile (k rows = t rows of this block)
    #pragma unroll
    for (int i = 0; i < 4; i++) {
        int idx = tid + i * 256;
        int r = idx >> 4, cg = idx & 15;
        float4 v = *(const float4*)(g_k + (size_t)(rowg0 + r) * Hn + cg * 4);
        u32* H = (u32*)&Khi[r * 72 + cg * 4];
        u32* L = (u32*)&Klo[r * 72 + cg * 4];
        H[0] = pack_hi(v.x, v.y); H[1] = pack_hi(v.z, v.w);
        L[0] = pack_lo(v.x, v.y); L[1] = pack_lo(v.z, v.w);
    }
    __syncthreads();

    const int r0loc = warp_m * 16 + g4;     // this thread's two rows: r0loc, r0loc+8
    float oacc[4][4];
    #pragma unroll
    for (int nt = 0; nt < 4; nt++)
        #pragma unroll
        for (int e = 0; e < 4; e++) oacc[nt][e] = 0.f;

    for (int st = 0; st <= qt; st++) {
        // ---- stage Q (into QP) and V, bf16 hi/lo ----
        #pragma unroll
        for (int i = 0; i < 4; i++) {
            int idx = tid + i * 256;
            int r = idx >> 4, cg = idx & 15;
            float4 vq = *(const float4*)(g_q + (size_t)(b * Tn + st * 64 + r) * Hn + cg * 4);
            u32* H = (u32*)&QPhi[r * 72 + cg * 4];
            u32* L = (u32*)&QPlo[r * 72 + cg * 4];
            H[0] = pack_hi(vq.x, vq.y); H[1] = pack_hi(vq.z, vq.w);
            L[0] = pack_lo(vq.x, vq.y); L[1] = pack_lo(vq.z, vq.w);
            float4 vv = *(const float4*)(g_v + (size_t)(b * Tn + st * 64 + r) * Hn + cg * 4);
            H = (u32*)&Vhi[r * 72 + cg * 4];
            L = (u32*)&Vlo[r * 72 + cg * 4];
            H[0] = pack_hi(vv.x, vv.y); H[1] = pack_hi(vv.z, vv.w);
            L[0] = pack_lo(vv.x, vv.y); L[1] = pack_lo(vv.z, vv.w);
        }
        __syncthreads();

        // ---- S = K . Q^T  (A = K[t][h], B = Q[s][h] non-trans) ----
        float sv[4][4];
        #pragma unroll
        for (int nt = 0; nt < 4; nt++)
            #pragma unroll
            for (int e = 0; e < 4; e++) sv[nt][e] = 0.f;

        #pragma unroll
        for (int ks = 0; ks < 4; ks++) {
            const int k0 = ks * 16;
            u32 ah[4], al[4];
            u32 aoff = 2u * ((warp_m * 16 + a_row) * 72 + k0 + a_kof);
            ldm4(ah[0], ah[1], ah[2], ah[3], KhiS + aoff);
            ldm4(al[0], al[1], al[2], al[3], KloS + aoff);
            u32 bh[2][4], bl[2][4];
            #pragma unroll
            for (int h = 0; h < 2; h++) {
                u32 boff = 2u * ((warp_n * 32 + h * 16 + bn_row) * 72 + k0 + bn_kof);
                ldm4(bh[h][0], bh[h][1], bh[h][2], bh[h][3], QPhiS + boff);
                ldm4(bl[h][0], bl[h][1], bl[h][2], bl[h][3], QPloS + boff);
            }
            #pragma unroll
            for (int h = 0; h < 2; h++)
                #pragma unroll
                for (int j = 0; j < 2; j++) {
                    float* c = sv[h * 2 + j];
                    mma_bf16(c, ah, &bh[h][2 * j]);
                    mma_bf16(c, ah, &bl[h][2 * j]);
                    mma_bf16(c, al, &bh[h][2 * j]);
                }
        }

        // scale (+mask on diagonal tile)
        #pragma unroll
        for (int nt = 0; nt < 4; nt++)
            #pragma unroll
            for (int e = 0; e < 4; e++) sv[nt][e] *= SCL;
        if (st == qt) {
            #pragma unroll
            for (int nt = 0; nt < 4; nt++) {
                int col = warp_n * 32 + nt * 8 + 2 * t4;
                if (col     > r0loc)     sv[nt][0] = -1e30f;
                if (col + 1 > r0loc)     sv[nt][1] = -1e30f;
                if (col     > r0loc + 8) sv[nt][2] = -1e30f;
                if (col + 1 > r0loc + 8) sv[nt][3] = -1e30f;
            }
        }

        // ---- row max (thread-local -> t4 shfl -> cross-warp smem) ----
        float mx0 = -1e30f, mx1 = -1e30f;
        #pragma unroll
        for (int nt = 0; nt < 4; nt++) {
            mx0 = fmaxf(mx0, fmaxf(sv[nt][0], sv[nt][1]));
            mx1 = fmaxf(mx1, fmaxf(sv[nt][2], sv[nt][3]));
        }
        mx0 = fmaxf(mx0, __shfl_xor_sync(0xffffffffu, mx0, 1));
        mx0 = fmaxf(mx0, __shfl_xor_sync(0xffffffffu, mx0, 2));
        mx1 = fmaxf(mx1, __shfl_xor_sync(0xffffffffu, mx1, 1));
        mx1 = fmaxf(mx1, __shfl_xor_sync(0xffffffffu, mx1, 2));
        if (t4 == 0) {
            pm[warp_n * 64 + r0loc]     = mx0;
            pm[warp_n * 64 + r0loc + 8] = mx1;
        }
        __syncthreads();
        if (tid < 64) {
            float mold = m_s[tid];
            float mnew = fmaxf(mold, fmaxf(pm[tid], pm[64 + tid]));
            float f = ex2(mold - mnew);
            m_s[tid] = mnew; f_s[tid] = f; l_s[tid] *= f;
        }
        __syncthreads();

        // ---- p = 2^(s-m); write P (bf16 hi/lo) into QP; rescale O ----
        float m0 = m_s[r0loc], m1 = m_s[r0loc + 8];
        float f0 = f_s[r0loc], f1 = f_s[r0loc + 8];
        #pragma unroll
        for (int nt = 0; nt < 4; nt++) {
            oacc[nt][0] *= f0; oacc[nt][1] *= f0;
            oacc[nt][2] *= f1; oacc[nt][3] *= f1;
        }
        float ps0 = 0.f, ps1 = 0.f;
        #pragma unroll
        for (int nt = 0; nt < 4; nt++) {
            float p0 = ex2(sv[nt][0] - m0);
            float p1 = ex2(sv[nt][1] - m0);
            float p2 = ex2(sv[nt][2] - m1);
            float p3 = ex2(sv[nt][3] - m1);
            ps0 += p0 + p1; ps1 += p2 + p3;
            int col = warp_n * 32 + nt * 8 + 2 * t4;
            *(u32*)&QPhi[r0loc * 72 + col]       = pack_hi(p0, p1);
            *(u32*)&QPlo[r0loc * 72 + col]       = pack_lo(p0, p1);
            *(u32*)&QPhi[(r0loc + 8) * 72 + col] = pack_hi(p2, p3);
            *(u32*)&QPlo[(r0loc + 8) * 72 + col] = pack_lo(p2, p3);
        }
        ps0 += __shfl_xor_sync(0xffffffffu, ps0, 1);
        ps0 += __shfl_xor_sync(0xffffffffu, ps0, 2);
        ps1 += __shfl_xor_sync(0xffffffffu, ps1, 1);
        ps1 += __shfl_xor_sync(0xffffffffu, ps1, 2);
        if (t4 == 0) {
            pm[warp_n * 64 + r0loc]     = ps0;
            pm[warp_n * 64 + r0loc + 8] = ps1;
        }
        __syncthreads();
        if (tid < 64) l_s[tid] += pm[tid] + pm[64 + tid];

        // ---- O += P @ V  (A = P[t][s], B = V[s][h] trans) ----
        #pragma unroll
        for (int ks = 0; ks < 4; ks++) {
            const int k0 = ks * 16;
            u32 ah[4], al[4];
            u32 aoff = 2u * ((warp_m * 16 + a_row) * 72 + k0 + a_kof);
            ldm4(ah[0], ah[1], ah[2], ah[3], QPhiS + aoff);
            ldm4(al[0], al[1], al[2], al[3], QPloS + aoff);
            u32 bh[2][4], bl[2][4];
            #pragma unroll
            for (int h = 0; h < 2; h++) {
                u32 boff = 2u * ((k0 + bt_krow) * 72 + warp_n * 32 + h * 16 + bt_nof);
                ldm4t(bh[h][0], bh[h][1], bh[h][2], bh[h][3], VhiS + boff);
                ldm4t(bl[h][0], bl[h][1], bl[h][2], bl[h][3], VloS + boff);
            }
            #pragma unroll
            for (int h = 0; h < 2; h++)
                #pragma unroll
                for (int j = 0; j < 2; j++) {
                    float* c = oacc[h * 2 + j];
                    mma_bf16(c, ah, &bh[h][2 * j]);
                    mma_bf16(c, ah, &bl[h][2 * j]);
                    mma_bf16(c, al, &bh[h][2 * j]);
                }
        }
        __syncthreads();
    }

    // ---- epilogue: divide by l, store ----
    float inv0 = 1.f / l_s[r0loc];
    float inv1 = 1.f / l_s[r0loc + 8];
    #pragma unroll
    for (int nt = 0; nt < 4; nt++) {
        int col = warp_n * 32 + nt * 8 + 2 * t4;
        *(float2*)(out + (size_t)(rowg0 + r0loc)     * Hn + col) =
            make_float2(oacc[nt][0] * inv0, oacc[nt][1] * inv0);
        *(float2*)(out + (size_t)(rowg0 + r0loc + 8) * Hn + col) =
            make_float2(oacc[nt][2] * inv1, oacc[nt][3] * inv1);
    }
}

// ---------------------------------------------------------------------------
extern "C" void kernel_launch(void* const* d_in, const int* in_sizes, int n_in,
                              void* d_out, int out_size)
{
    const float* x  = (const float*)d_in[0];
    const float* Wq = (const float*)d_in[1];
    const float* Wk = (const float*)d_in[2];
    const float* Wv = (const float*)d_in[3];
    float* out = (float*)d_out;

    cudaFuncSetAttribute(attn_bf16, cudaFuncAttributeMaxDynamicSharedMemorySize, ATTN_SMEM);

    qkv_bf16<<<dim3(3, Mtot / 128), 256>>>(x, Wq, Wk, Wv);
    attn_bf16<<<dim3(4, Bn), 256, ATTN_SMEM>>>(out);
}